// round 12
// baseline (speedup 1.0000x reference)
#include <cuda_runtime.h>
#include <cuda_bf16.h>
#include <cstdint>

// Problem constants (fixed shapes per reference setup_inputs)
#define IN_CH        10
#define OUT_CH       32
#define NUM_PILLARS  50000
#define EPS          1e-3f
#define TPB          256
#define PPB          256   // points per block (8 warps x 32 points)
#define SSTRIDE      12    // padded shared stride (16B-aligned rows)

// Scratch (device globals: allocation-free, graph-safe)
__device__ __align__(128) float g_Wf[IN_CH * OUT_CH];          // folded W, [k][c]
__device__ __align__(128) float g_bf[OUT_CH];                  // folded bias
__device__ __align__(128) float g_pmax[NUM_PILLARS * OUT_CH];  // pillar max (6.4 MB)

// ---------------------------------------------------------------------------
// Kernel 1: fold BN into linear weights.  W is [OUT_CH, IN_CH] row-major.
//   x_bn = in @ (W*s)^T + (beta - mean*s),  s = gamma * rsqrt(var+eps)
// ---------------------------------------------------------------------------
__global__ void fold_params_kernel(const float* __restrict__ W,
                                   const float* __restrict__ gamma,
                                   const float* __restrict__ beta,
                                   const float* __restrict__ mean,
                                   const float* __restrict__ var) {
    int c = threadIdx.x;
    if (c >= OUT_CH) return;
    float s = rsqrtf(var[c] + EPS) * gamma[c];
#pragma unroll
    for (int k = 0; k < IN_CH; k++) {
        g_Wf[k * OUT_CH + c] = W[c * IN_CH + k] * s;
    }
    g_bf[c] = beta[c] - mean[c] * s;
}

// ---------------------------------------------------------------------------
// Kernel 2: zero the pillar-max buffer (float4 stores).
// ---------------------------------------------------------------------------
__global__ void init_pmax_kernel() {
    int i = blockIdx.x * blockDim.x + threadIdx.x;
    const int n4 = (NUM_PILLARS * OUT_CH) / 4;
    if (i < n4) {
        reinterpret_cast<float4*>(g_pmax)[i] = make_float4(0.f, 0.f, 0.f, 0.f);
    }
}

// ---------------------------------------------------------------------------
// Kernel 3: main pass.  8 lanes x float4 channels == 4 points per warp
// instruction; 8 iterations cover the warp's 32 points.
//   *** R11: weights + bias live in SHARED (not 40 registers) and
//   __launch_bounds__(256, 6) caps regs at ~42 -> 6 blocks/SM = 75% occ
//   (R3/R10 variants all sat at 3 blocks/SM = ~34-50% and ~107-122 us). ***
//   - inputs staged to shared (stride 12, 16B-aligned rows, conflict-free)
//   - sW reads: 8 distinct float4 addrs/warp, point-invariant -> conflict-free
//   - ReLU, STG.128 of out[i, c0:c0+4]
//   - snapshot-guarded atomicMax (x>=0: int cmp == float cmp), R3 form
// ---------------------------------------------------------------------------
__global__ __launch_bounds__(TPB, 6) void pfn_main_kernel(
    const float* __restrict__ in,
    const int*   __restrict__ inv,
    float*       __restrict__ out,
    int n) {
    __shared__ float sIn[PPB * SSTRIDE];          // 12 KB
    __shared__ float sW[IN_CH * OUT_CH];          // 1.25 KB, [k][c]
    __shared__ float sB[OUT_CH];

    const int t    = threadIdx.x;
    const int lane = t & 31;
    const int warp = t >> 5;
    const int c0   = (lane & 7) * 4;       // this thread's 4 channels
    const int blockStart = blockIdx.x * PPB;
    const int nPts = min(PPB, n - blockStart);

    // load folded weights + bias into shared (note: 320 > TPB, loop needed)
    for (int idx = t; idx < IN_CH * OUT_CH; idx += TPB) sW[idx] = g_Wf[idx];
    if (t < OUT_CH) sB[t] = g_bf[t];

    // stage inputs: coalesced float4 global loads, scatter to stride-12 shared
    {
        const int nFloats = nPts * IN_CH;
        const int nF4 = nFloats >> 2;
        const float* gin = in + (size_t)blockStart * IN_CH;
        const float4* gin4 = reinterpret_cast<const float4*>(gin);
        for (int idx = t; idx < nF4; idx += TPB) {
            float4 v = gin4[idx];
            int g = idx * 4;
            sIn[(g / IN_CH) * SSTRIDE + (g % IN_CH)] = v.x;  g++;
            sIn[(g / IN_CH) * SSTRIDE + (g % IN_CH)] = v.y;  g++;
            sIn[(g / IN_CH) * SSTRIDE + (g % IN_CH)] = v.z;  g++;
            sIn[(g / IN_CH) * SSTRIDE + (g % IN_CH)] = v.w;
        }
        for (int idx = (nF4 << 2) + t; idx < nFloats; idx += TPB)
            sIn[(idx / IN_CH) * SSTRIDE + (idx % IN_CH)] = gin[idx];
    }
    __syncthreads();

    const int pbase = blockStart + warp * 32;
    int iv = 0;
    if (pbase + lane < n) iv = inv[pbase + lane];

    const float4 bv = *reinterpret_cast<const float4*>(&sB[c0]);

#pragma unroll 2
    for (int it = 0; it < 8; it++) {
        const int j = it * 4 + (lane >> 3);                 // local point id
        const int i = pbase + j;
        const int p = __shfl_sync(0xffffffffu, iv, j);      // full-warp shfl
        if (i < n) {
            const float* xr = sIn + (warp * 32 + j) * SSTRIDE;
            float xk[IN_CH];
            {   // 2x LDS.128 + 2x LDS.32 (16B-aligned rows)
                float4 a = *reinterpret_cast<const float4*>(xr);
                float4 b = *reinterpret_cast<const float4*>(xr + 4);
                xk[0]=a.x; xk[1]=a.y; xk[2]=a.z; xk[3]=a.w;
                xk[4]=b.x; xk[5]=b.y; xk[6]=b.z; xk[7]=b.w;
                xk[8]=xr[8]; xk[9]=xr[9];
            }
            float4 acc = bv;
#pragma unroll
            for (int k = 0; k < IN_CH; k++) {
                const float4 w = *reinterpret_cast<const float4*>(&sW[k * OUT_CH + c0]);
                acc.x = fmaf(xk[k], w.x, acc.x);
                acc.y = fmaf(xk[k], w.y, acc.y);
                acc.z = fmaf(xk[k], w.z, acc.z);
                acc.w = fmaf(xk[k], w.w, acc.w);
            }
            acc.x = fmaxf(acc.x, 0.f); acc.y = fmaxf(acc.y, 0.f);
            acc.z = fmaxf(acc.z, 0.f); acc.w = fmaxf(acc.w, 0.f);

            // first half of output row, fully coalesced STG.128
            *reinterpret_cast<float4*>(&out[(size_t)i * 64 + c0]) = acc;

            // snapshot-guarded scatter-max (values >= 0: int cmp == float cmp)
            float* pmf = &g_pmax[p * OUT_CH + c0];
            float4 cur = *reinterpret_cast<const float4*>(pmf);
            int* pm = reinterpret_cast<int*>(pmf);
            if (acc.x > cur.x) atomicMax(pm + 0, __float_as_int(acc.x));
            if (acc.y > cur.y) atomicMax(pm + 1, __float_as_int(acc.y));
            if (acc.z > cur.z) atomicMax(pm + 2, __float_as_int(acc.z));
            if (acc.w > cur.w) atomicMax(pm + 3, __float_as_int(acc.w));
        }
    }
}

// ---------------------------------------------------------------------------
// Kernel 4: gather: out[i, 32:64] = pmax[inv[i], :].  Same 4-points-per-
// instruction layout: LDG.128 from L2-resident pmax, coalesced STG.128.
// (Unchanged: 28 regs, 88% occ, ~60% DRAM — near its wall.)
// ---------------------------------------------------------------------------
__global__ __launch_bounds__(TPB) void pfn_gather_kernel(
    const int* __restrict__ inv,
    float*     __restrict__ out,
    int n) {
    const int t    = threadIdx.x;
    const int lane = t & 31;
    const int warp = t >> 5;
    const int c0   = (lane & 7) * 4;
    const int pbase = blockIdx.x * PPB + warp * 32;

    int iv = 0;
    if (pbase + lane < n) iv = inv[pbase + lane];

#pragma unroll
    for (int it = 0; it < 8; it++) {
        const int j = it * 4 + (lane >> 3);
        const int i = pbase + j;
        const int p = __shfl_sync(0xffffffffu, iv, j);
        if (i < n) {
            float4 v = *reinterpret_cast<const float4*>(&g_pmax[p * OUT_CH + c0]);
            *reinterpret_cast<float4*>(&out[(size_t)i * 64 + 32 + c0]) = v;
        }
    }
}

// ---------------------------------------------------------------------------
// Launch.  Input order: inputs, unq_inv, W, gamma, beta, running_mean,
// running_var[, num_out_inds].
// ---------------------------------------------------------------------------
extern "C" void kernel_launch(void* const* d_in, const int* in_sizes, int n_in,
                              void* d_out, int out_size) {
    const float* in    = (const float*)d_in[0];
    const int*   inv   = (const int*)d_in[1];
    const float* W     = (const float*)d_in[2];
    const float* gamma = (const float*)d_in[3];
    const float* beta  = (const float*)d_in[4];
    const float* mean  = (const float*)d_in[5];
    const float* var   = (const float*)d_in[6];
    float* out = (float*)d_out;

    const int n = in_sizes[1];  // number of points (unq_inv element count)

    fold_params_kernel<<<1, 32>>>(W, gamma, beta, mean, var);

    const int n4 = (NUM_PILLARS * OUT_CH) / 4;
    init_pmax_kernel<<<(n4 + TPB - 1) / TPB, TPB>>>();

    const int nBlocks = (n + PPB - 1) / PPB;
    pfn_main_kernel<<<nBlocks, TPB>>>(in, inv, out, n);

    pfn_gather_kernel<<<nBlocks, TPB>>>(inv, out, n);
}

// round 16
// speedup vs baseline: 1.6319x; 1.6319x over previous
#include <cuda_runtime.h>
#include <cuda_bf16.h>
#include <cstdint>

// Problem constants (fixed shapes per reference setup_inputs)
#define IN_CH        10
#define OUT_CH       32
#define NUM_PILLARS  50000
#define EPS          1e-3f
#define TPB          256
#define PPB          256   // points per block (8 warps x 32 points)
#define SSTRIDE      12    // padded shared stride (16B-aligned rows)

// Scratch (device globals: allocation-free, graph-safe)
__device__ __align__(128) float g_Wf[IN_CH * OUT_CH];          // folded W, [k][c]
__device__ __align__(128) float g_bf[OUT_CH];                  // folded bias
__device__ __align__(128) float g_pmax[NUM_PILLARS * OUT_CH];  // pillar max (6.4 MB)

// ---------------------------------------------------------------------------
// Kernel 1 (merged prep): zero pillar-max buffer; block 0 folds BN into W.
//   x_bn = in @ (W*s)^T + (beta - mean*s),  s = gamma * rsqrt(var+eps)
// (Correctness of this merged form proven in rounds 4/6; saves one launch
//  and ~3 us of strictly-serial prologue vs. separate fold+init.)
// ---------------------------------------------------------------------------
__global__ void prep_kernel(const float* __restrict__ W,
                            const float* __restrict__ gamma,
                            const float* __restrict__ beta,
                            const float* __restrict__ mean,
                            const float* __restrict__ var) {
    if (blockIdx.x == 0 && threadIdx.x < OUT_CH) {
        int c = threadIdx.x;
        float s = rsqrtf(var[c] + EPS) * gamma[c];
#pragma unroll
        for (int k = 0; k < IN_CH; k++)
            g_Wf[k * OUT_CH + c] = W[c * IN_CH + k] * s;
        g_bf[c] = beta[c] - mean[c] * s;
    }
    int i = blockIdx.x * blockDim.x + threadIdx.x;
    const int n4 = (NUM_PILLARS * OUT_CH) / 4;
    if (i < n4)
        reinterpret_cast<float4*>(g_pmax)[i] = make_float4(0.f, 0.f, 0.f, 0.f);
}

// ---------------------------------------------------------------------------
// Kernel 2: main pass (exact measured-best R3 form, 159.8 us x3 runs).
// 8 lanes x float4 channels == 4 points per warp instruction; 8 iterations
// cover the warp's 32 points.
//   - inputs staged to shared (stride 12, 16B-aligned rows, conflict-free)
//   - thread's 4-channel weight columns in registers (10 x float4)
//   - ReLU, STG.128 of out[i, c0:c0+4]
//   - snapshot-guarded atomicMax into L2-resident pillar buffer
//     (values >= 0: signed-int compare == float compare on the bit pattern;
//      guard earns its L2 reads by suppressing atomic serialization — R9
//      measured +17 us without it)
// ---------------------------------------------------------------------------
__global__ __launch_bounds__(TPB) void pfn_main_kernel(
    const float* __restrict__ in,
    const int*   __restrict__ inv,
    float*       __restrict__ out,
    int n) {
    __shared__ float sIn[PPB * SSTRIDE];   // 12 KB

    const int t    = threadIdx.x;
    const int lane = t & 31;
    const int warp = t >> 5;
    const int c0   = (lane & 7) * 4;       // this thread's 4 channels
    const int blockStart = blockIdx.x * PPB;
    const int nPts = min(PPB, n - blockStart);

    // per-thread folded weight columns + bias (4 channels)
    float4 wv[IN_CH];
#pragma unroll
    for (int k = 0; k < IN_CH; k++)
        wv[k] = *reinterpret_cast<const float4*>(&g_Wf[k * OUT_CH + c0]);
    const float4 bv = *reinterpret_cast<const float4*>(&g_bf[c0]);

    // stage inputs: coalesced float4 global loads, scatter to stride-12 shared
    {
        const int nFloats = nPts * IN_CH;
        const int nF4 = nFloats >> 2;
        const float* gin = in + (size_t)blockStart * IN_CH;
        const float4* gin4 = reinterpret_cast<const float4*>(gin);
        for (int idx = t; idx < nF4; idx += TPB) {
            float4 v = gin4[idx];
            int g = idx * 4;
            sIn[(g / IN_CH) * SSTRIDE + (g % IN_CH)] = v.x;  g++;
            sIn[(g / IN_CH) * SSTRIDE + (g % IN_CH)] = v.y;  g++;
            sIn[(g / IN_CH) * SSTRIDE + (g % IN_CH)] = v.z;  g++;
            sIn[(g / IN_CH) * SSTRIDE + (g % IN_CH)] = v.w;
        }
        for (int idx = (nF4 << 2) + t; idx < nFloats; idx += TPB)
            sIn[(idx / IN_CH) * SSTRIDE + (idx % IN_CH)] = gin[idx];
    }
    __syncthreads();

    const int pbase = blockStart + warp * 32;
    int iv = 0;
    if (pbase + lane < n) iv = inv[pbase + lane];

#pragma unroll
    for (int it = 0; it < 8; it++) {
        const int j = it * 4 + (lane >> 3);                 // local point id
        const int i = pbase + j;
        const int p = __shfl_sync(0xffffffffu, iv, j);      // full-warp shfl
        if (i < n) {
            const float* xr = sIn + (warp * 32 + j) * SSTRIDE;
            float xk[IN_CH];
            {   // 2x LDS.128 + 2x LDS.32 (16B-aligned rows)
                float4 a = *reinterpret_cast<const float4*>(xr);
                float4 b = *reinterpret_cast<const float4*>(xr + 4);
                xk[0]=a.x; xk[1]=a.y; xk[2]=a.z; xk[3]=a.w;
                xk[4]=b.x; xk[5]=b.y; xk[6]=b.z; xk[7]=b.w;
                xk[8]=xr[8]; xk[9]=xr[9];
            }
            float4 acc = bv;
#pragma unroll
            for (int k = 0; k < IN_CH; k++) {
                acc.x = fmaf(xk[k], wv[k].x, acc.x);
                acc.y = fmaf(xk[k], wv[k].y, acc.y);
                acc.z = fmaf(xk[k], wv[k].z, acc.z);
                acc.w = fmaf(xk[k], wv[k].w, acc.w);
            }
            acc.x = fmaxf(acc.x, 0.f); acc.y = fmaxf(acc.y, 0.f);
            acc.z = fmaxf(acc.z, 0.f); acc.w = fmaxf(acc.w, 0.f);

            // first half of output row, fully coalesced STG.128
            *reinterpret_cast<float4*>(&out[(size_t)i * 64 + c0]) = acc;

            // snapshot-guarded scatter-max
            float* pmf = &g_pmax[p * OUT_CH + c0];
            float4 cur = *reinterpret_cast<const float4*>(pmf);
            int* pm = reinterpret_cast<int*>(pmf);
            if (acc.x > cur.x) atomicMax(pm + 0, __float_as_int(acc.x));
            if (acc.y > cur.y) atomicMax(pm + 1, __float_as_int(acc.y));
            if (acc.z > cur.z) atomicMax(pm + 2, __float_as_int(acc.z));
            if (acc.w > cur.w) atomicMax(pm + 3, __float_as_int(acc.w));
        }
    }
}

// ---------------------------------------------------------------------------
// Kernel 3: gather: out[i, 32:64] = pmax[inv[i], :].  Exact measured form
// (43.5-44.7 us, ~60% DRAM, LTS-bound).  LDG.128 from L2-resident pmax,
// coalesced STG.128.
// ---------------------------------------------------------------------------
__global__ __launch_bounds__(TPB) void pfn_gather_kernel(
    const int* __restrict__ inv,
    float*     __restrict__ out,
    int n) {
    const int t    = threadIdx.x;
    const int lane = t & 31;
    const int warp = t >> 5;
    const int c0   = (lane & 7) * 4;
    const int pbase = blockIdx.x * PPB + warp * 32;

    int iv = 0;
    if (pbase + lane < n) iv = inv[pbase + lane];

#pragma unroll
    for (int it = 0; it < 8; it++) {
        const int j = it * 4 + (lane >> 3);
        const int i = pbase + j;
        const int p = __shfl_sync(0xffffffffu, iv, j);
        if (i < n) {
            float4 v = *reinterpret_cast<const float4*>(&g_pmax[p * OUT_CH + c0]);
            *reinterpret_cast<float4*>(&out[(size_t)i * 64 + 32 + c0]) = v;
        }
    }
}

// ---------------------------------------------------------------------------
// Launch.  Input order: inputs, unq_inv, W, gamma, beta, running_mean,
// running_var[, num_out_inds].
// ---------------------------------------------------------------------------
extern "C" void kernel_launch(void* const* d_in, const int* in_sizes, int n_in,
                              void* d_out, int out_size) {
    const float* in    = (const float*)d_in[0];
    const int*   inv   = (const int*)d_in[1];
    const float* W     = (const float*)d_in[2];
    const float* gamma = (const float*)d_in[3];
    const float* beta  = (const float*)d_in[4];
    const float* mean  = (const float*)d_in[5];
    const float* var   = (const float*)d_in[6];
    float* out = (float*)d_out;

    const int n = in_sizes[1];  // number of points (unq_inv element count)

    const int n4 = (NUM_PILLARS * OUT_CH) / 4;
    prep_kernel<<<(n4 + TPB - 1) / TPB, TPB>>>(W, gamma, beta, mean, var);

    const int nBlocks = (n + PPB - 1) / PPB;
    pfn_main_kernel<<<nBlocks, TPB>>>(in, inv, out, n);

    pfn_gather_kernel<<<nBlocks, TPB>>>(inv, out, n);
}